// round 11
// baseline (speedup 1.0000x reference)
#include <cuda_runtime.h>
#include <cuda_bf16.h>
#include <stdint.h>

// TargetEncoder: out[b, v] = f32( bf16( max over t with ids[b,t]==v of w[b,t], 0 baseline ) )
// ids: (1024,256) int32; w: (1024,256) f32; out: (1024,30522) f32.
//
// R8/R9 post-mortem: SMEM-staged version touched every output byte 3x
// (STS+LDS+STG) with 2 barriers and pushed the 125 MB to DRAM via .cs hints;
// effective ceiling is the L2/LTS write path (~6300 B/cyc, output fits in the
// 126 MB L2), so minimize instructions and keep lines L2-resident:
//   Kernel A: pure float4 zero-fill (plain stores, write-allocate).
//   Kernel B: one RED.MAX per token. Values f32(bf16(w)) >= 0 and baseline 0,
//             so signed-int atomicMax == float max (bit-exact; bf16 RN rounding
//             is monotone so round-then-max == max-then-round).

static constexpr int B_ROWS = 1024;
static constexpr int V      = 30522;
static constexpr int S      = 256;
static constexpr int N_TOK  = B_ROWS * S;              // 262144
static constexpr int N_F4   = B_ROWS * V / 4;          // 7,813,632 float4 (exact)

__global__ __launch_bounds__(512) void fill_zero_kernel(float4* __restrict__ out)
{
    const float4 z = make_float4(0.f, 0.f, 0.f, 0.f);
    int i = blockIdx.x * 512 + threadIdx.x;
    const int stride = gridDim.x * 512;
    for (; i < N_F4; i += stride) {
        out[i] = z;                       // plain STG.128 -> write-allocate in L2
    }
}

__global__ __launch_bounds__(512) void scatter_max_kernel(
    const int*   __restrict__ ids,   // (B, S) int32
    const float* __restrict__ w,     // (B, S) float32
    int*         __restrict__ out)   // (B, V) float32 viewed as int32
{
    const int t = blockIdx.x * 512 + threadIdx.x;      // token index
    if (t >= N_TOK) return;
    const int b = t >> 8;                              // row  (S == 256)
    int v = ids[t];
    if (v < 0) v = 0; else if (v >= V) v = V - 1;      // safety clamp
    // f32(bf16(w)) bit pattern: bf16 bits shifted to the high half.
    const unsigned short h = __bfloat16_as_ushort(__float2bfloat16(w[t]));
    const int bits = (int)((unsigned)h << 16);         // >= 0 since w in [0,1)
    atomicMax(out + (size_t)b * V + v, bits);          // RED.MAX, no return
}

extern "C" void kernel_launch(void* const* d_in, const int* in_sizes, int n_in,
                              void* d_out, int out_size)
{
    const int*   ids = (const int*)  d_in[0];
    const float* wts = (const float*)d_in[1];

    // Fill: ~1184 CTAs (8 per SM) x 512 threads, grid-stride.
    fill_zero_kernel<<<1184, 512>>>((float4*)d_out);
    // Scatter: one thread per token; stream order enforces fill-before-scatter.
    scatter_max_kernel<<<N_TOK / 512, 512>>>(ids, wts, (int*)d_out);
}

// round 13
// speedup vs baseline: 1.0938x; 1.0938x over previous
#include <cuda_runtime.h>
#include <cuda_bf16.h>
#include <stdint.h>

// TargetEncoder: out[b, v] = f32( bf16( max over t with ids[b,t]==v of w[b,t], 0 baseline ) )
// ids: (1024,256) int32; w: (1024,256) f32; out: (1024,30522) f32. 125 MB write.
//
// R8/R9/R11 established: bulk write of 125 MB runs ~5.8 TB/s (L2 write+drain
// wall) regardless of store flavor; a separate scatter kernel adds its full
// latency (7.2 us). This version fuses scatter into the fill with ZERO smem:
//   per-row CTA: prefetch (id,w) -> stream zeros (float2) -> __syncthreads
//   -> one RED.MAX per token on int-viewed float (values >= 0, baseline 0,
//   so signed-int max == float max; bf16 RN rounding is monotone => bit-exact).
// (R12 run of this exact source died to a container-infra failure; resubmit.)

static constexpr int B_ROWS  = 1024;
static constexpr int V       = 30522;
static constexpr int S       = 256;
static constexpr int THREADS = 256;
static constexpr int N2      = V / 2;          // 15261 float2 per row

__global__ __launch_bounds__(THREADS) void target_encoder_kernel(
    const int*   __restrict__ ids,   // (B, S) int32
    const float* __restrict__ w,     // (B, S) float32
    float*       __restrict__ out)   // (B, V) float32
{
    const int b   = blockIdx.x;
    const int tid = threadIdx.x;

    // --- 0. prefetch this row's token (THREADS == S): hides LDG under the stream
    int v = ids[b * S + tid];
    const float f = w[b * S + tid];
    if (v < 0) v = 0; else if (v >= V) v = V - 1;          // safety clamp
    const unsigned short h = __bfloat16_as_ushort(__float2bfloat16(f));
    const int bits = (int)((unsigned)h << 16);             // f32(bf16(f)) bits, >= 0

    // --- 1. stream the row to zero (float2; row byte base b*122088 is 8B-aligned)
    float2* dst = reinterpret_cast<float2*>(out + (size_t)b * V);
    const float2 z = make_float2(0.f, 0.f);
    #pragma unroll 8
    for (int i = tid; i < N2; i += THREADS) {              // ~60 iters/thread
        dst[i] = z;
    }
    __syncthreads();   // CTA's zero stores ordered before its patches

    // --- 2. patch: one RED.MAX per token (duplicates in-row resolved by atomic)
    atomicMax(reinterpret_cast<int*>(out) + (size_t)b * V + v, bits);
}

extern "C" void kernel_launch(void* const* d_in, const int* in_sizes, int n_in,
                              void* d_out, int out_size)
{
    const int*   ids = (const int*)  d_in[0];
    const float* wts = (const float*)d_in[1];
    float*       out = (float*)      d_out;

    target_encoder_kernel<<<B_ROWS, THREADS>>>(ids, wts, out);
}

// round 15
// speedup vs baseline: 1.1338x; 1.0366x over previous
#include <cuda_runtime.h>
#include <cuda_bf16.h>
#include <stdint.h>

// TargetEncoder: out[b, v] = f32( bf16( max over t with ids[b,t]==v of w[b,t], 0 baseline ) )
// ids: (1024,256) int32; w: (1024,256) f32; out: (1024,30522) f32. 125 MB write.
//
// Steady-state finding (R8 vs R13): plain stores leave 125 MB dirty in the
// 126 MB L2; every replay then stalls on writeback-before-allocate (wall 26.3
// vs flushed-cache ncu 22.7). __stcs evict-first keeps L2 clean -> wall ==
// profile (R8: 23.0/22.1). So: minimal instruction stream + .cs policy.
//   - CTA = 2 consecutive rows: 244176 B contiguous, 16B-divisible -> float4
//     __stcs zero stream (half the store instructions of float2).
//   - fused patch: one RED.MAX per token on int-viewed f32 (values >= 0,
//     baseline 0 -> int max == float max; bf16 RN monotone -> bit-exact).
//   - 512 CTAs x 512 threads -> single wave on 148 SMs.

static constexpr int B_ROWS  = 1024;
static constexpr int V       = 30522;
static constexpr int S       = 256;
static constexpr int THREADS = 512;
static constexpr int N4      = 2 * V / 4;      // 15261 float4 per 2-row region (exact)

__global__ __launch_bounds__(THREADS) void target_encoder_kernel(
    const int*   __restrict__ ids,   // (B, S) int32
    const float* __restrict__ w,     // (B, S) float32
    float*       __restrict__ out)   // (B, V) float32
{
    const int c   = blockIdx.x;      // row pair: rows 2c, 2c+1
    const int tid = threadIdx.x;

    // --- 0. prefetch this pair's token (512 tokens == THREADS) ---
    //     token tid -> row 2c + (tid>>8), slot tid&255; flat index = c*512 + tid
    int v = ids[c * 2 * S + tid];
    const float f = w[c * 2 * S + tid];
    if (v < 0) v = 0; else if (v >= V) v = V - 1;          // safety clamp
    const unsigned short h = __bfloat16_as_ushort(__float2bfloat16(f));
    const int bits = (int)((unsigned)h << 16);             // f32(bf16(f)) bits, >= 0

    // --- 1. stream the 2-row region to zero (float4 .cs; base 16B-aligned) ---
    float4* dst = reinterpret_cast<float4*>(out + (size_t)c * 2 * V);
    const float4 z = make_float4(0.f, 0.f, 0.f, 0.f);
    #pragma unroll 5
    for (int i = tid; i < N4; i += THREADS) {              // ~30 iters/thread
        __stcs(dst + i, z);
    }
    __syncthreads();   // CTA's zeros ordered before its patches

    // --- 2. patch: one RED.MAX per token (in-row duplicates resolved by atomic)
    const int row = 2 * c + (tid >> 8);
    atomicMax(reinterpret_cast<int*>(out) + (size_t)row * V + v, bits);
}

extern "C" void kernel_launch(void* const* d_in, const int* in_sizes, int n_in,
                              void* d_out, int out_size)
{
    const int*   ids = (const int*)  d_in[0];
    const float* wts = (const float*)d_in[1];
    float*       out = (float*)      d_out;

    target_encoder_kernel<<<B_ROWS / 2, THREADS>>>(ids, wts, out);
}